// round 14
// baseline (speedup 1.0000x reference)
#include <cuda_runtime.h>
#include <cuda_bf16.h>
#include <cstdint>
#include <cstddef>

#define BB 16
#define NN 458
#define DD 128
#define EE 42240
#define NROWS (BB * NN)
#define AGG_STRIDE (BB * NN * DD)
#define N_ITEMS 672
#define EDGE_GRID 148

// ---------------------------------------------------------------------------
// Scratch (device globals)
// ---------------------------------------------------------------------------
__device__ float g_x  [BB * NN * DD];
__device__ float g_u  [BB * NN * DD];
__device__ float g_v  [BB * NN * DD];
__device__ float g_agg[8 * BB * NN * DD];
__device__ uint4 g_ebf[BB * EE * 16];            // edge_attr bf16x2 packed
__device__ __align__(16) float g_wtf[9 * 17408]; // node W tf32(RNA), padded 136

// ---------------------------------------------------------------------------
// helpers
// ---------------------------------------------------------------------------
__device__ __forceinline__ uint32_t packbf(float lo, float hi) {
    uint32_t r;
    asm("cvt.rn.bf16x2.f32 %0, %1, %2;" : "=r"(r) : "f"(hi), "f"(lo));
    return r;
}
__device__ __forceinline__ float to_tf32(float x) {
    uint32_t u;
    asm("cvt.rna.tf32.f32 %0, %1;" : "=r"(u) : "f"(x));
    return __uint_as_float(u);
}
__device__ __forceinline__ uint32_t smem_u32(const void* p) {
    uint32_t a;
    asm("{ .reg .u64 t; cvta.to.shared.u64 t, %1; cvt.u32.u64 %0, t; }"
        : "=r"(a) : "l"(p));
    return a;
}
__device__ __forceinline__ void mma16(float& c0, float& c1, float& c2, float& c3,
                                      uint32_t a0, uint32_t a1, uint32_t a2, uint32_t a3,
                                      uint32_t b0, uint32_t b1) {
    asm volatile(
        "mma.sync.aligned.m16n8k16.row.col.f32.bf16.bf16.f32 "
        "{%0,%1,%2,%3},{%4,%5,%6,%7},{%8,%9},{%0,%1,%2,%3};"
        : "+f"(c0), "+f"(c1), "+f"(c2), "+f"(c3)
        : "r"(a0), "r"(a1), "r"(a2), "r"(a3), "r"(b0), "r"(b1));
}
__device__ __forceinline__ void mma8(float& c0, float& c1, float& c2, float& c3,
                                     uint32_t a0, uint32_t a1, uint32_t a2, uint32_t a3,
                                     uint32_t b0, uint32_t b1) {
    asm volatile(
        "mma.sync.aligned.m16n8k8.row.col.f32.tf32.tf32.f32 "
        "{%0,%1,%2,%3},{%4,%5,%6,%7},{%8,%9},{%0,%1,%2,%3};"
        : "+f"(c0), "+f"(c1), "+f"(c2), "+f"(c3)
        : "r"(a0), "r"(a1), "r"(a2), "r"(a3), "r"(b0), "r"(b1));
}
__device__ __forceinline__ void ldsm_x4(uint32_t& r0, uint32_t& r1, uint32_t& r2,
                                        uint32_t& r3, uint32_t addr) {
    asm volatile("ldmatrix.sync.aligned.m8n8.x4.shared.b16 {%0,%1,%2,%3}, [%4];"
                 : "=r"(r0), "=r"(r1), "=r"(r2), "=r"(r3) : "r"(addr));
}
__device__ __forceinline__ void cp16(uint32_t daddr, const void* gptr, uint32_t srcsize) {
    asm volatile("cp.async.cg.shared.global [%0], [%1], 16, %2;"
                 :: "r"(daddr), "l"(gptr), "r"(srcsize) : "memory");
}

// ---------------------------------------------------------------------------
// prepack_wt: 9 node matrices (l x {self=0, src=1, dst=2}) -> tf32 RNA, pad 136
// ---------------------------------------------------------------------------
__global__ __launch_bounds__(256) void prepack_wt(const float* __restrict__ w_self,
                                                  const float* __restrict__ w_msg)
{
    const int m = blockIdx.x, l = m / 3, k = m % 3;
    const float* src = (k == 0) ? (w_self + (size_t)l * 16384)
                                : (w_msg + (size_t)l * 49152 + (size_t)(k - 1) * 16384);
    float* out = g_wtf + (size_t)m * 17408;
    for (int i = threadIdx.x; i < 17408; i += 256) {
        const int kr = i / 136, c = i % 136;
        out[i] = (c < 128) ? to_tf32(src[kr * 128 + c]) : 0.f;
    }
}

// ---------------------------------------------------------------------------
// persistent edge kernel: 148 CTAs, 512 threads.
// ea != nullptr (layer 0): stage A from fp32 edge_attr inline (LDG+pack+STS)
//   AND write the packed image to g_ebf for layers 1-2.
// ea == nullptr (layers 1-2): stage A from g_ebf via cp.async.
// ---------------------------------------------------------------------------
#define EW_SW 0
#define EW_SA 8704
#define EW_SV (EW_SA + 3 * 4352)
#define EW_SU (EW_SV + 64 * 132)
#define EDGE_SMEM_WORDS (EW_SU + 3 * 512)
#define EDGE_SMEM_BYTES (EDGE_SMEM_WORDS * 4)

__global__ __launch_bounds__(512, 1) void edge_kernel(const float* __restrict__ wl,
                                                      const float* __restrict__ ea)
{
    extern __shared__ uint32_t smw[];
    uint32_t* sWp = smw + EW_SW;
    float* sV = (float*)(smw + EW_SV);
    float* sU = (float*)(smw + EW_SU);
    const uint32_t sb = smem_u32(smw);
    const int tid = threadIdx.x;

    {
        const float* wedge = wl + 256 * 128;
        for (int i = tid; i < 8192; i += 512) {
            const int kp = i >> 7, n = i & 127;
            sWp[kp * 136 + n] = packbf(wedge[(2 * kp) * 128 + n],
                                       wedge[(2 * kp + 1) * 128 + n]);
        }
    }
    __syncthreads();

    const int w    = tid >> 5;
    const int lane = tid & 31;
    const int wm   = w & 3;
    const int wn   = w >> 2;
    const int g    = lane >> 2;
    const int tig  = lane & 3;

    uint32_t bB[8][4][2];
    #pragma unroll
    for (int ks = 0; ks < 8; ks++)
        #pragma unroll
        for (int nt = 0; nt < 4; nt++) {
            const int n = wn * 32 + nt * 8 + g;
            bB[ks][nt][0] = sWp[(ks * 8 + tig) * 136 + n];
            bB[ks][nt][1] = sWp[(ks * 8 + tig + 4) * 136 + n];
        }

    const int quad  = lane >> 3;
    const int r8    = lane & 7;
    const int rowL  = wm * 16 + (quad & 1) * 8 + r8;
    const int koffL = (quad >> 1) * 4;
    const uint32_t aAddr0 = sb + (EW_SA + rowL * 68 + koffL) * 4u;

    const int nsrc_a[4] = {64, 128, 128, 128};
    const int ndst_a[4] = {128, 128, 128, 10};
    const int eb_a  [4] = {0, 8192, 24576, 40960};
    const int so_a  [4] = {0, 64, 192, 320};
    const int do_a  [4] = {64, 192, 320, 448};

    for (int item = blockIdx.x; item < N_ITEMS; item += EDGE_GRID) {
        const int b = item / 42, r = item % 42;
        int lb, dtile, chunk, s_begin;
        if (r < 8)       { lb = 0; dtile = r >> 2;          chunk = r & 3;  s_begin = chunk * 16; }
        else if (r < 24) { lb = 1; const int q = r - 8;  dtile = q & 1; chunk = q >> 1; s_begin = chunk * 16; }
        else if (r < 40) { lb = 2; const int q = r - 24; dtile = q & 1; chunk = q >> 1; s_begin = chunk * 16; }
        else             { lb = 3; const int q = r - 40; dtile = 0;     chunk = q * 4;  s_begin = q * 64; }

        const int n_src = nsrc_a[lb];
        const int n_dst = ndst_a[lb];
        const int ebase = eb_a[lb];
        const int soff  = so_a[lb];
        const int doff  = do_a[lb];
        const int d0    = dtile * 64;
        const bool packed4 = (lb == 3);
        const int sshift = packed4 ? 4 : 6;
        const int rmask  = packed4 ? 15 : 63;
        const int sstep  = packed4 ? 4 : 1;
        const int nsrow  = packed4 ? 4 : 1;

        auto stageA = [&](int buf, int i) {
            const int s0 = s_begin + i * sstep;
            if (ea == nullptr) {
                // layers 1-2: cp.async from packed g_ebf
                const uint32_t dbase = sb + (EW_SA + buf * 4352) * 4;
                #pragma unroll
                for (int j = 0; j < 2; j++) {
                    const int idx = tid + 512 * j;
                    const int row = idx >> 4, c = idx & 15;
                    const int dgl = row & rmask;
                    const int s   = s0 + (row >> sshift);
                    const bool ok = (d0 + dgl < n_dst);
                    const size_t e = (size_t)b * EE + ebase +
                                     (ok ? ((size_t)s * n_dst + d0 + dgl) : 0);
                    cp16(dbase + (uint32_t)(row * 68 + c * 4) * 4u,
                         g_ebf + e * 16 + c, ok ? 16u : 0u);
                }
            } else {
                // layer 0: fp32 -> bf16 pack inline; also persist to g_ebf
                uint32_t* dsm = smw + EW_SA + buf * 4352;
                #pragma unroll
                for (int j = 0; j < 2; j++) {
                    const int idx = tid + 512 * j;
                    const int row = idx >> 4, c = idx & 15;
                    const int dgl = row & rmask;
                    const int s   = s0 + (row >> sshift);
                    const bool ok = (d0 + dgl < n_dst);
                    uint4 pk = make_uint4(0u, 0u, 0u, 0u);
                    if (ok) {
                        const size_t e = (size_t)b * EE + ebase +
                                         (size_t)s * n_dst + d0 + dgl;
                        const float* p = ea + e * DD + c * 8;
                        const float4 f0 = *(const float4*)p;
                        const float4 f1 = *(const float4*)(p + 4);
                        pk = make_uint4(packbf(f0.x, f0.y), packbf(f0.z, f0.w),
                                        packbf(f1.x, f1.y), packbf(f1.z, f1.w));
                        g_ebf[e * 16 + c] = pk;
                    }
                    *(uint4*)(dsm + row * 68 + c * 4) = pk;
                }
            }
        };
        auto stageU = [&](int slot, int i) {
            if (tid < 32 * nsrow) {
                const int sl = tid >> 5, c4 = tid & 31;
                cp16(sb + (EW_SU + slot * 512 + sl * 128 + c4 * 4) * 4u,
                     g_u + ((size_t)b * NN + soff + s_begin + i * sstep + sl) * DD + c4 * 4,
                     16u);
            }
        };

        stageA(0, 0); stageU(0, 0);
        asm volatile("cp.async.commit_group;" ::: "memory");
        stageA(1, 1); stageU(1, 1);
        asm volatile("cp.async.commit_group;" ::: "memory");

        for (int i = tid; i < 2048; i += 512) {
            const int row = i >> 5, c4 = i & 31;
            const int dgl = row & rmask;
            float4 v4 = make_float4(0.f, 0.f, 0.f, 0.f);
            if (d0 + dgl < n_dst)
                v4 = *(const float4*)(g_v + ((size_t)b * NN + doff + d0 + dgl) * DD + c4 * 4);
            *(float4*)(sV + row * 132 + c4 * 4) = v4;
        }
        asm volatile("cp.async.wait_group 1;" ::: "memory");
        __syncthreads();

        float agg[4][4];
        #pragma unroll
        for (int nt = 0; nt < 4; nt++)
            #pragma unroll
            for (int rr = 0; rr < 4; rr++) agg[nt][rr] = 0.f;

        for (int i = 0; i < 16; i++) {
            const int p = i % 3;
            if (i + 2 < 16) {
                stageA((i + 2) % 3, i + 2);
                stageU((i + 2) % 3, i + 2);
            }
            asm volatile("cp.async.commit_group;" ::: "memory");

            float acc[4][4];
            #pragma unroll
            for (int nt = 0; nt < 4; nt++)
                #pragma unroll
                for (int rr = 0; rr < 4; rr++) acc[nt][rr] = 0.f;

            const uint32_t aBase = aAddr0 + (uint32_t)p * (4352u * 4u);
            #pragma unroll
            for (int ks = 0; ks < 8; ks++) {
                uint32_t a0, a1, a2, a3;
                ldsm_x4(a0, a1, a2, a3, aBase + (uint32_t)ks * 32u);
                #pragma unroll
                for (int nt = 0; nt < 4; nt++)
                    mma16(acc[nt][0], acc[nt][1], acc[nt][2], acc[nt][3],
                          a0, a1, a2, a3, bB[ks][nt][0], bB[ks][nt][1]);
            }

            const float* sUp = sU + p * 512 + (packed4 ? wm * 128 : 0);
            const int r0 = wm * 16 + g;
            #pragma unroll
            for (int nt = 0; nt < 4; nt++) {
                const int col = wn * 32 + nt * 8 + 2 * tig;
                const float2 uu = *(const float2*)(sUp + col);
                const float2 v0 = *(const float2*)(sV + r0 * 132 + col);
                const float2 v1 = *(const float2*)(sV + (r0 + 8) * 132 + col);
                agg[nt][0] += fmaxf(acc[nt][0] + uu.x + v0.x, 0.f);
                agg[nt][1] += fmaxf(acc[nt][1] + uu.y + v0.y, 0.f);
                agg[nt][2] += fmaxf(acc[nt][2] + uu.x + v1.x, 0.f);
                agg[nt][3] += fmaxf(acc[nt][3] + uu.y + v1.y, 0.f);
            }

            asm volatile("cp.async.wait_group 1;" ::: "memory");
            __syncthreads();
        }

        const float scale = 1.f / (float)n_src;
        const int chunkbuf = packed4 ? (chunk + wm) : chunk;
        float* aggbuf = g_agg + (size_t)chunkbuf * AGG_STRIDE;
        const int dg0 = d0 + ((wm * 16 + g) & rmask);
        const int dg1 = d0 + ((wm * 16 + g + 8) & rmask);
        #pragma unroll
        for (int nt = 0; nt < 4; nt++) {
            const int col = wn * 32 + nt * 8 + 2 * tig;
            if (dg0 < n_dst)
                *(float2*)(aggbuf + ((size_t)b * NN + doff + dg0) * DD + col) =
                    make_float2(agg[nt][0] * scale, agg[nt][1] * scale);
            if (dg1 < n_dst)
                *(float2*)(aggbuf + ((size_t)b * NN + doff + dg1) * DD + col) =
                    make_float2(agg[nt][2] * scale, agg[nt][3] * scale);
        }
        __syncthreads();
    }
}

// ---------------------------------------------------------------------------
// self_uv_tf32: 64-row tiles, 115 CTAs, 512 threads, tf32 mma, prepacked W.
//   self mode  (m0>=0): G0=Wself->W0, G1=Wsrc->W1, G2(after gemm1)=Wdst->W0
//                       gemm1: W0; gemm2: W1; gemm3: W0.
//   uv-only    (m0<0):  G0=Wsrc->W0, G1=Wdst->W1; gemm2: W0; gemm3: W1.
// ---------------------------------------------------------------------------
#define SV_W0 0
#define SV_W1 17408
#define SV_XS 34816
#define SV_XN 43264
#define SV_WORDS 51712
#define SV_SMEM_BYTES (SV_WORDS * 4)

__global__ __launch_bounds__(512, 1) void self_uv_tf32(const float* __restrict__ xin,
                                                       int m0,
                                                       const float* __restrict__ bself,
                                                       int msrc,
                                                       const float* __restrict__ bnext)
{
    extern __shared__ float smf[];
    float* W0 = smf + SV_W0;
    float* W1 = smf + SV_W1;
    float* xs = smf + SV_XS;
    float* xn = smf + SV_XN;
    const uint32_t sb = smem_u32(smf);

    const int tid  = threadIdx.x;
    const int row0 = blockIdx.x * 64;
    const float* x = (xin != nullptr) ? xin : g_x;
    const bool selfmode = (m0 >= 0);
    const bool have_uv  = (msrc >= 0);

    auto stageW = [&](int wbuf, int m) {
        const uint32_t dbase = sb + (wbuf ? SV_W1 : SV_W0) * 4u;
        const float* src = g_wtf + (size_t)m * 17408;
        #pragma unroll
        for (int j = 0; j < 9; j++) {
            const int i = tid + 512 * j;
            if (i < 4352) cp16(dbase + (uint32_t)i * 16u, src + i * 4, 16u);
        }
    };

    stageW(0, selfmode ? m0 : msrc);
    asm volatile("cp.async.commit_group;" ::: "memory");
    if (have_uv) stageW(1, selfmode ? msrc : (msrc + 1));
    asm volatile("cp.async.commit_group;" ::: "memory");

    {
        float* xt = selfmode ? xs : xn;
        for (int i = tid; i < 2048; i += 512) {
            const int rr = i >> 5, c4 = i & 31;
            const int row = row0 + rr;
            float4 xv = make_float4(0.f, 0.f, 0.f, 0.f);
            if (row < NROWS)
                xv = *(const float4*)(x + (size_t)row * DD + c4 * 4);
            xv.x = to_tf32(xv.x); xv.y = to_tf32(xv.y);
            xv.z = to_tf32(xv.z); xv.w = to_tf32(xv.w);
            *(float4*)(xt + rr * 132 + c4 * 4) = xv;
        }
    }
    asm volatile("cp.async.wait_group 1;" ::: "memory");
    __syncthreads();

    const int w    = tid >> 5;
    const int lane = tid & 31;
    const int wm   = w & 3;
    const int wn   = w >> 2;
    const int g    = lane >> 2;
    const int tig  = lane & 3;
    const int rowg0 = row0 + wm * 16 + g;

    auto gemm = [&](const float* A, const float* W, float (&acc)[4][4]) {
        #pragma unroll
        for (int nt = 0; nt < 4; nt++)
            #pragma unroll
            for (int rr = 0; rr < 4; rr++) acc[nt][rr] = 0.f;
        const uint32_t* Au = (const uint32_t*)A;
        const uint32_t* Wu = (const uint32_t*)W;
        const int base0 = (wm * 16 + g) * 132;
        #pragma unroll
        for (int ks = 0; ks < 16; ks++) {
            const int kb = ks * 8;
            const uint32_t a0 = Au[base0 + kb + tig];
            const uint32_t a1 = Au[base0 + 8 * 132 + kb + tig];
            const uint32_t a2 = Au[base0 + kb + tig + 4];
            const uint32_t a3 = Au[base0 + 8 * 132 + kb + tig + 4];
            #pragma unroll
            for (int nt = 0; nt < 4; nt++) {
                const int n = wn * 32 + nt * 8 + g;
                const uint32_t b0 = Wu[(kb + tig) * 136 + n];
                const uint32_t b1 = Wu[(kb + tig + 4) * 136 + n];
                mma8(acc[nt][0], acc[nt][1], acc[nt][2], acc[nt][3],
                     a0, a1, a2, a3, b0, b1);
            }
        }
    };

    if (selfmode) {
        float acc[4][4];
        gemm(xs, W0, acc);

        #pragma unroll
        for (int rr = 0; rr < 2; rr++) {
            const int row = rowg0 + rr * 8;
            const bool valid = (row < NROWS);
            const int nodeidx = row % NN;
            const bool hasagg = valid && (nodeidx >= 64);
            const int nbuf = (nodeidx < 192) ? 4 : 8;
            #pragma unroll
            for (int nt = 0; nt < 4; nt++) {
                const int col = wn * 32 + nt * 8 + 2 * tig;
                float c0 = acc[nt][rr * 2 + 0] + __ldg(bself + col);
                float c1 = acc[nt][rr * 2 + 1] + __ldg(bself + col + 1);
                if (hasagg) {
                    const size_t o = (size_t)row * DD + col;
                    for (int cb = 0; cb < nbuf; cb++) {
                        const float2 av = *(const float2*)(g_agg + (size_t)cb * AGG_STRIDE + o);
                        c0 += av.x; c1 += av.y;
                    }
                }
                c0 = fmaxf(c0, 0.f);
                c1 = fmaxf(c1, 0.f);
                if (valid)
                    *(float2*)(g_x + (size_t)row * DD + col) = make_float2(c0, c1);
                *(float2*)(xn + (wm * 16 + g + rr * 8) * 132 + col) =
                    make_float2(to_tf32(c0), to_tf32(c1));
            }
        }
        __syncthreads();
        if (have_uv) {
            stageW(0, msrc + 1);
            asm volatile("cp.async.commit_group;" ::: "memory");
        }
    }

    if (have_uv) {
        asm volatile("cp.async.wait_group 1;" ::: "memory");
        {
            float acc[4][4];
            gemm(xn, selfmode ? W1 : W0, acc);
            #pragma unroll
            for (int rr = 0; rr < 2; rr++) {
                const int row = rowg0 + rr * 8;
                if (row < NROWS) {
                    #pragma unroll
                    for (int nt = 0; nt < 4; nt++) {
                        const int col = wn * 32 + nt * 8 + 2 * tig;
                        *(float2*)(g_u + (size_t)row * DD + col) =
                            make_float2(acc[nt][rr * 2 + 0], acc[nt][rr * 2 + 1]);
                    }
                }
            }
        }
        asm volatile("cp.async.wait_group 0;" ::: "memory");
        __syncthreads();
        {
            float acc[4][4];
            gemm(xn, selfmode ? W0 : W1, acc);
            #pragma unroll
            for (int rr = 0; rr < 2; rr++) {
                const int row = rowg0 + rr * 8;
                if (row < NROWS) {
                    #pragma unroll
                    for (int nt = 0; nt < 4; nt++) {
                        const int col = wn * 32 + nt * 8 + 2 * tig;
                        *(float2*)(g_v + (size_t)row * DD + col) =
                            make_float2(acc[nt][rr * 2 + 0] + __ldg(bnext + col),
                                        acc[nt][rr * 2 + 1] + __ldg(bnext + col + 1));
                    }
                }
            }
        }
    }
}

// ---------------------------------------------------------------------------
// head kernel
// ---------------------------------------------------------------------------
__global__ __launch_bounds__(128) void head_kernel(const float* __restrict__ w1,
                                                   const float* __restrict__ b1,
                                                   const float* __restrict__ w2,
                                                   const float* __restrict__ b2,
                                                   const float* __restrict__ w3,
                                                   const float* __restrict__ b3,
                                                   float* __restrict__ out)
{
    __shared__ float g[128];
    __shared__ float h[128];
    const int b = blockIdx.x;
    const int t = threadIdx.x;

    float s = 0.f;
    const float* xb = g_x + (size_t)b * NN * DD;
    for (int n = 0; n < NN; n++) s += xb[(size_t)n * DD + t];
    g[t] = s * (1.f / (float)NN);
    __syncthreads();

    float acc = 0.f;
    #pragma unroll 4
    for (int k = 0; k < 128; k++) acc += g[k] * __ldg(w1 + k * 128 + t);
    h[t] = fmaxf(acc + b1[t], 0.f);
    __syncthreads();

    acc = 0.f;
    #pragma unroll 4
    for (int k = 0; k < 128; k++) acc += h[k] * __ldg(w2 + k * 128 + t);
    __syncthreads();
    g[t] = fmaxf(acc + b2[t], 0.f);
    __syncthreads();

    if (t < 10) {
        float o = b3[t];
        for (int k = 0; k < 128; k++) o += g[k] * __ldg(w3 + k * 10 + t);
        out[b * 10 + t] = o;
    }
}

// ---------------------------------------------------------------------------
// launch
// ---------------------------------------------------------------------------
extern "C" void kernel_launch(void* const* d_in, const int* in_sizes, int n_in,
                              void* d_out, int out_size)
{
    (void)in_sizes; (void)n_in; (void)out_size;
    const float* node_features = (const float*)d_in[0];
    const float* edge_attr     = (const float*)d_in[1];
    const float* w_msg         = (const float*)d_in[2];
    const float* b_msg         = (const float*)d_in[3];
    const float* w_self        = (const float*)d_in[4];
    const float* b_self        = (const float*)d_in[5];
    const float* w1            = (const float*)d_in[6];
    const float* b1            = (const float*)d_in[7];
    const float* w2            = (const float*)d_in[8];
    const float* b2            = (const float*)d_in[9];
    const float* w3            = (const float*)d_in[10];
    const float* b3            = (const float*)d_in[11];
    float* out = (float*)d_out;

    cudaFuncSetAttribute(edge_kernel, cudaFuncAttributeMaxDynamicSharedMemorySize,
                         EDGE_SMEM_BYTES);
    cudaFuncSetAttribute(self_uv_tf32, cudaFuncAttributeMaxDynamicSharedMemorySize,
                         SV_SMEM_BYTES);

    prepack_wt<<<9, 256>>>(w_self, w_msg);

    // layer-0: uv-only mode (msrc = matrix idx of layer-0 Wsrc = 1)
    self_uv_tf32<<<115, 512, SV_SMEM_BYTES>>>(node_features, -1, nullptr, 1, b_msg);

    for (int l = 0; l < 3; l++) {
        const float* wl = w_msg + (size_t)l * 384 * 128;
        // layer 0 converts fp32 edge_attr inline and persists g_ebf
        edge_kernel<<<EDGE_GRID, 512, EDGE_SMEM_BYTES>>>(
            wl, (l == 0) ? edge_attr : nullptr);

        const float* xin = (l == 0) ? node_features : nullptr;
        const int msrc = (l < 2) ? (3 * (l + 1) + 1) : -1;
        const float* bn = (l < 2) ? (b_msg + (size_t)(l + 1) * 128) : nullptr;
        self_uv_tf32<<<115, 512, SV_SMEM_BYTES>>>(xin, 3 * l,
                                                  b_self + (size_t)l * 128, msrc, bn);
    }
    head_kernel<<<16, 128>>>(w1, b1, w2, b2, w3, b3, out);
}

// round 15
// speedup vs baseline: 1.0422x; 1.0422x over previous
#include <cuda_runtime.h>
#include <cuda_bf16.h>
#include <cstdint>
#include <cstddef>

#define BB 16
#define NN 458
#define DD 128
#define EE 42240
#define NROWS (BB * NN)
#define AGG_STRIDE (BB * NN * DD)
#define N_ITEMS 672
#define EDGE_GRID 148

// ---------------------------------------------------------------------------
// Scratch (device globals)
// ---------------------------------------------------------------------------
__device__ float g_x  [BB * NN * DD];
__device__ float g_u  [BB * NN * DD];
__device__ float g_v  [BB * NN * DD];
__device__ float g_agg[8 * BB * NN * DD];
__device__ uint4 g_ebf[BB * EE * 16];            // edge_attr bf16x2 packed
__device__ __align__(16) float g_wtf[9 * 17408]; // node W tf32(RNA), padded 136

// ---------------------------------------------------------------------------
// helpers
// ---------------------------------------------------------------------------
__device__ __forceinline__ uint32_t packbf(float lo, float hi) {
    uint32_t r;
    asm("cvt.rn.bf16x2.f32 %0, %1, %2;" : "=r"(r) : "f"(hi), "f"(lo));
    return r;
}
__device__ __forceinline__ float to_tf32(float x) {
    uint32_t u;
    asm("cvt.rna.tf32.f32 %0, %1;" : "=r"(u) : "f"(x));
    return __uint_as_float(u);
}
__device__ __forceinline__ uint32_t smem_u32(const void* p) {
    uint32_t a;
    asm("{ .reg .u64 t; cvta.to.shared.u64 t, %1; cvt.u32.u64 %0, t; }"
        : "=r"(a) : "l"(p));
    return a;
}
__device__ __forceinline__ void mma16(float& c0, float& c1, float& c2, float& c3,
                                      uint32_t a0, uint32_t a1, uint32_t a2, uint32_t a3,
                                      uint32_t b0, uint32_t b1) {
    asm volatile(
        "mma.sync.aligned.m16n8k16.row.col.f32.bf16.bf16.f32 "
        "{%0,%1,%2,%3},{%4,%5,%6,%7},{%8,%9},{%0,%1,%2,%3};"
        : "+f"(c0), "+f"(c1), "+f"(c2), "+f"(c3)
        : "r"(a0), "r"(a1), "r"(a2), "r"(a3), "r"(b0), "r"(b1));
}
__device__ __forceinline__ void mma8(float& c0, float& c1, float& c2, float& c3,
                                     uint32_t a0, uint32_t a1, uint32_t a2, uint32_t a3,
                                     uint32_t b0, uint32_t b1) {
    asm volatile(
        "mma.sync.aligned.m16n8k8.row.col.f32.tf32.tf32.f32 "
        "{%0,%1,%2,%3},{%4,%5,%6,%7},{%8,%9},{%0,%1,%2,%3};"
        : "+f"(c0), "+f"(c1), "+f"(c2), "+f"(c3)
        : "r"(a0), "r"(a1), "r"(a2), "r"(a3), "r"(b0), "r"(b1));
}
__device__ __forceinline__ void ldsm_x4(uint32_t& r0, uint32_t& r1, uint32_t& r2,
                                        uint32_t& r3, uint32_t addr) {
    asm volatile("ldmatrix.sync.aligned.m8n8.x4.shared.b16 {%0,%1,%2,%3}, [%4];"
                 : "=r"(r0), "=r"(r1), "=r"(r2), "=r"(r3) : "r"(addr));
}
__device__ __forceinline__ void cp16(uint32_t daddr, const void* gptr, uint32_t srcsize) {
    asm volatile("cp.async.cg.shared.global [%0], [%1], 16, %2;"
                 :: "r"(daddr), "l"(gptr), "r"(srcsize) : "memory");
}

// ---------------------------------------------------------------------------
// prepack_wt: 9 node matrices (l x {self=0, src=1, dst=2}) -> tf32 RNA, pad 136
// ---------------------------------------------------------------------------
__global__ __launch_bounds__(256) void prepack_wt(const float* __restrict__ w_self,
                                                  const float* __restrict__ w_msg)
{
    const int m = blockIdx.x, l = m / 3, k = m % 3;
    const float* src = (k == 0) ? (w_self + (size_t)l * 16384)
                                : (w_msg + (size_t)l * 49152 + (size_t)(k - 1) * 16384);
    float* out = g_wtf + (size_t)m * 17408;
    for (int i = threadIdx.x; i < 17408; i += 256) {
        const int kr = i / 136, c = i % 136;
        out[i] = (c < 128) ? to_tf32(src[kr * 128 + c]) : 0.f;
    }
}

// ---------------------------------------------------------------------------
// persistent edge kernel: 148 CTAs, 512 threads.
// Layer 0 (ea != nullptr): cp.async fp32 tiles into fp32 smem (2-deep), then an
//   async-covered smem->smem bf16 conversion feeds ldsm AND persists g_ebf.
// Layers 1-2 (ea == nullptr): cp.async bf16 tiles from g_ebf (3-deep), as R13.
// ---------------------------------------------------------------------------
#define EW_SW 0
#define EW_SA 8704                      // bf16 A bufs (3 x 4352 words)
#define EW_SV (EW_SA + 3 * 4352)        // V 64x132 fp32
#define EW_SU (EW_SV + 64 * 132)        // U 3 x 512
#define EW_A32 (EW_SU + 3 * 512)        // fp32 A bufs (2 x 8448 words), layer 0
#define EDGE_SMEM_WORDS (EW_A32 + 2 * 8448)
#define EDGE_SMEM_BYTES (EDGE_SMEM_WORDS * 4)

__global__ __launch_bounds__(512, 1) void edge_kernel(const float* __restrict__ wl,
                                                      const float* __restrict__ ea)
{
    extern __shared__ uint32_t smw[];
    uint32_t* sWp = smw + EW_SW;
    float* sV = (float*)(smw + EW_SV);
    float* sU = (float*)(smw + EW_SU);
    const uint32_t sb = smem_u32(smw);
    const int tid = threadIdx.x;
    const bool l0 = (ea != nullptr);

    {
        const float* wedge = wl + 256 * 128;
        for (int i = tid; i < 8192; i += 512) {
            const int kp = i >> 7, n = i & 127;
            sWp[kp * 136 + n] = packbf(wedge[(2 * kp) * 128 + n],
                                       wedge[(2 * kp + 1) * 128 + n]);
        }
    }
    __syncthreads();

    const int w    = tid >> 5;
    const int lane = tid & 31;
    const int wm   = w & 3;
    const int wn   = w >> 2;
    const int g    = lane >> 2;
    const int tig  = lane & 3;

    uint32_t bB[8][4][2];
    #pragma unroll
    for (int ks = 0; ks < 8; ks++)
        #pragma unroll
        for (int nt = 0; nt < 4; nt++) {
            const int n = wn * 32 + nt * 8 + g;
            bB[ks][nt][0] = sWp[(ks * 8 + tig) * 136 + n];
            bB[ks][nt][1] = sWp[(ks * 8 + tig + 4) * 136 + n];
        }

    const int quad  = lane >> 3;
    const int r8    = lane & 7;
    const int rowL  = wm * 16 + (quad & 1) * 8 + r8;
    const int koffL = (quad >> 1) * 4;
    const uint32_t aAddr0 = sb + (EW_SA + rowL * 68 + koffL) * 4u;

    const int nsrc_a[4] = {64, 128, 128, 128};
    const int ndst_a[4] = {128, 128, 128, 10};
    const int eb_a  [4] = {0, 8192, 24576, 40960};
    const int so_a  [4] = {0, 64, 192, 320};
    const int do_a  [4] = {64, 192, 320, 448};

    for (int item = blockIdx.x; item < N_ITEMS; item += EDGE_GRID) {
        const int b = item / 42, r = item % 42;
        int lb, dtile, chunk, s_begin;
        if (r < 8)       { lb = 0; dtile = r >> 2;          chunk = r & 3;  s_begin = chunk * 16; }
        else if (r < 24) { lb = 1; const int q = r - 8;  dtile = q & 1; chunk = q >> 1; s_begin = chunk * 16; }
        else if (r < 40) { lb = 2; const int q = r - 24; dtile = q & 1; chunk = q >> 1; s_begin = chunk * 16; }
        else             { lb = 3; const int q = r - 40; dtile = 0;     chunk = q * 4;  s_begin = q * 64; }

        const int n_src = nsrc_a[lb];
        const int n_dst = ndst_a[lb];
        const int ebase = eb_a[lb];
        const int soff  = so_a[lb];
        const int doff  = do_a[lb];
        const int d0    = dtile * 64;
        const bool packed4 = (lb == 3);
        const int sshift = packed4 ? 4 : 6;
        const int rmask  = packed4 ? 15 : 63;
        const int sstep  = packed4 ? 4 : 1;
        const int nsrow  = packed4 ? 4 : 1;

        // ---- layers 1-2: cp.async bf16 tile from g_ebf ----
        auto stageA = [&](int buf, int i) {
            const uint32_t dbase = sb + (EW_SA + buf * 4352) * 4;
            const int s0 = s_begin + i * sstep;
            #pragma unroll
            for (int j = 0; j < 2; j++) {
                const int idx = tid + 512 * j;
                const int row = idx >> 4, c = idx & 15;
                const int dgl = row & rmask;
                const int s   = s0 + (row >> sshift);
                const bool ok = (d0 + dgl < n_dst);
                const size_t e = (size_t)b * EE + ebase +
                                 (ok ? ((size_t)s * n_dst + d0 + dgl) : 0);
                cp16(dbase + (uint32_t)(row * 68 + c * 4) * 4u,
                     g_ebf + e * 16 + c, ok ? 16u : 0u);
            }
        };
        // ---- layer 0: cp.async fp32 tile from edge_attr into fp32 buf ----
        auto stageA32 = [&](int i) {
            const uint32_t dbase = sb + (EW_A32 + (i & 1) * 8448) * 4;
            const int s0 = s_begin + i * sstep;
            #pragma unroll
            for (int j = 0; j < 4; j++) {
                const int idx = tid + 512 * j;
                const int row = idx >> 5, c = idx & 31;
                const int dgl = row & rmask;
                const int s   = s0 + (row >> sshift);
                const bool ok = (d0 + dgl < n_dst);
                const size_t e = (size_t)b * EE + ebase +
                                 (ok ? ((size_t)s * n_dst + d0 + dgl) : 0);
                cp16(dbase + (uint32_t)(row * 132 + c * 4) * 4u,
                     ea + e * DD + c * 4, ok ? 16u : 0u);
            }
        };
        // ---- layer 0: fp32 smem -> bf16 smem (+ persist g_ebf) ----
        auto convert0 = [&](int tile) {
            const int s0 = s_begin + tile * sstep;
            const float* src = (const float*)(smw + EW_A32 + (tile & 1) * 8448);
            uint32_t* dst = smw + EW_SA + (tile & 1) * 4352;
            #pragma unroll
            for (int j = 0; j < 2; j++) {
                const int idx = tid + 512 * j;
                const int row = idx >> 4, cc = idx & 15;
                const float4 f0 = *(const float4*)(src + row * 132 + cc * 8);
                const float4 f1 = *(const float4*)(src + row * 132 + cc * 8 + 4);
                const uint4 pk = make_uint4(packbf(f0.x, f0.y), packbf(f0.z, f0.w),
                                            packbf(f1.x, f1.y), packbf(f1.z, f1.w));
                *(uint4*)(dst + row * 68 + cc * 4) = pk;
                const int dgl = row & rmask;
                const int s   = s0 + (row >> sshift);
                if (d0 + dgl < n_dst) {
                    const size_t e = (size_t)b * EE + ebase +
                                     (size_t)s * n_dst + d0 + dgl;
                    g_ebf[e * 16 + cc] = pk;
                }
            }
        };
        auto stageU = [&](int slot, int i) {
            if (tid < 32 * nsrow) {
                const int sl = tid >> 5, c4 = tid & 31;
                cp16(sb + (EW_SU + slot * 512 + sl * 128 + c4 * 4) * 4u,
                     g_u + ((size_t)b * NN + soff + s_begin + i * sstep + sl) * DD + c4 * 4,
                     16u);
            }
        };

        // ---- prologue ----
        if (l0) stageA32(0); else stageA(0, 0);
        stageU(0, 0);
        asm volatile("cp.async.commit_group;" ::: "memory");
        if (l0) stageA32(1); else stageA(1, 1);
        stageU(1, 1);
        asm volatile("cp.async.commit_group;" ::: "memory");

        for (int i = tid; i < 2048; i += 512) {
            const int row = i >> 5, c4 = i & 31;
            const int dgl = row & rmask;
            float4 v4 = make_float4(0.f, 0.f, 0.f, 0.f);
            if (d0 + dgl < n_dst)
                v4 = *(const float4*)(g_v + ((size_t)b * NN + doff + d0 + dgl) * DD + c4 * 4);
            *(float4*)(sV + row * 132 + c4 * 4) = v4;
        }
        asm volatile("cp.async.wait_group 1;" ::: "memory");
        if (l0) convert0(0);
        __syncthreads();

        float agg[4][4];
        #pragma unroll
        for (int nt = 0; nt < 4; nt++)
            #pragma unroll
            for (int rr = 0; rr < 4; rr++) agg[nt][rr] = 0.f;

        for (int i = 0; i < 16; i++) {
            const int pA = l0 ? (i & 1) : (i % 3);
            if (i + 2 < 16) {
                if (l0) stageA32(i + 2); else stageA((i + 2) % 3, i + 2);
                stageU((i + 2) % 3, i + 2);
            }
            asm volatile("cp.async.commit_group;" ::: "memory");

            float acc[4][4];
            #pragma unroll
            for (int nt = 0; nt < 4; nt++)
                #pragma unroll
                for (int rr = 0; rr < 4; rr++) acc[nt][rr] = 0.f;

            const uint32_t aBase = aAddr0 + (uint32_t)pA * (4352u * 4u);
            #pragma unroll
            for (int ks = 0; ks < 8; ks++) {
                uint32_t a0, a1, a2, a3;
                ldsm_x4(a0, a1, a2, a3, aBase + (uint32_t)ks * 32u);
                #pragma unroll
                for (int nt = 0; nt < 4; nt++)
                    mma16(acc[nt][0], acc[nt][1], acc[nt][2], acc[nt][3],
                          a0, a1, a2, a3, bB[ks][nt][0], bB[ks][nt][1]);
            }

            // layer 0: after HMMA issue, finish loads and convert the next tile
            if (l0) {
                asm volatile("cp.async.wait_group 1;" ::: "memory");
                if (i + 1 < 16) convert0(i + 1);
            }

            const float* sUp = sU + (i % 3) * 512 + (packed4 ? wm * 128 : 0);
            const int r0 = wm * 16 + g;
            #pragma unroll
            for (int nt = 0; nt < 4; nt++) {
                const int col = wn * 32 + nt * 8 + 2 * tig;
                const float2 uu = *(const float2*)(sUp + col);
                const float2 v0 = *(const float2*)(sV + r0 * 132 + col);
                const float2 v1 = *(const float2*)(sV + (r0 + 8) * 132 + col);
                agg[nt][0] += fmaxf(acc[nt][0] + uu.x + v0.x, 0.f);
                agg[nt][1] += fmaxf(acc[nt][1] + uu.y + v0.y, 0.f);
                agg[nt][2] += fmaxf(acc[nt][2] + uu.x + v1.x, 0.f);
                agg[nt][3] += fmaxf(acc[nt][3] + uu.y + v1.y, 0.f);
            }

            if (!l0)
                asm volatile("cp.async.wait_group 1;" ::: "memory");
            __syncthreads();
        }

        const float scale = 1.f / (float)n_src;
        const int chunkbuf = packed4 ? (chunk + wm) : chunk;
        float* aggbuf = g_agg + (size_t)chunkbuf * AGG_STRIDE;
        const int dg0 = d0 + ((wm * 16 + g) & rmask);
        const int dg1 = d0 + ((wm * 16 + g + 8) & rmask);
        #pragma unroll
        for (int nt = 0; nt < 4; nt++) {
            const int col = wn * 32 + nt * 8 + 2 * tig;
            if (dg0 < n_dst)
                *(float2*)(aggbuf + ((size_t)b * NN + doff + dg0) * DD + col) =
                    make_float2(agg[nt][0] * scale, agg[nt][1] * scale);
            if (dg1 < n_dst)
                *(float2*)(aggbuf + ((size_t)b * NN + doff + dg1) * DD + col) =
                    make_float2(agg[nt][2] * scale, agg[nt][3] * scale);
        }
        __syncthreads();
    }
}

// ---------------------------------------------------------------------------
// self_uv_tf32: 64-row tiles, 115 CTAs, 512 threads, tf32 mma, prepacked W.
//   self mode  (m0>=0): G0=Wself->W0, G1=Wsrc->W1, G2(after gemm1)=Wdst->W0
//                       gemm1: W0; gemm2: W1; gemm3: W0.
//   uv-only    (m0<0):  G0=Wsrc->W0, G1=Wdst->W1; gemm2: W0; gemm3: W1.
// ---------------------------------------------------------------------------
#define SV_W0 0
#define SV_W1 17408
#define SV_XS 34816
#define SV_XN 43264
#define SV_WORDS 51712
#define SV_SMEM_BYTES (SV_WORDS * 4)

__global__ __launch_bounds__(512, 1) void self_uv_tf32(const float* __restrict__ xin,
                                                       int m0,
                                                       const float* __restrict__ bself,
                                                       int msrc,
                                                       const float* __restrict__ bnext)
{
    extern __shared__ float smf[];
    float* W0 = smf + SV_W0;
    float* W1 = smf + SV_W1;
    float* xs = smf + SV_XS;
    float* xn = smf + SV_XN;
    const uint32_t sb = smem_u32(smf);

    const int tid  = threadIdx.x;
    const int row0 = blockIdx.x * 64;
    const float* x = (xin != nullptr) ? xin : g_x;
    const bool selfmode = (m0 >= 0);
    const bool have_uv  = (msrc >= 0);

    auto stageW = [&](int wbuf, int m) {
        const uint32_t dbase = sb + (wbuf ? SV_W1 : SV_W0) * 4u;
        const float* src = g_wtf + (size_t)m * 17408;
        #pragma unroll
        for (int j = 0; j < 9; j++) {
            const int i = tid + 512 * j;
            if (i < 4352) cp16(dbase + (uint32_t)i * 16u, src + i * 4, 16u);
        }
    };

    stageW(0, selfmode ? m0 : msrc);
    asm volatile("cp.async.commit_group;" ::: "memory");
    if (have_uv) stageW(1, selfmode ? msrc : (msrc + 1));
    asm volatile("cp.async.commit_group;" ::: "memory");

    {
        float* xt = selfmode ? xs : xn;
        for (int i = tid; i < 2048; i += 512) {
            const int rr = i >> 5, c4 = i & 31;
            const int row = row0 + rr;
            float4 xv = make_float4(0.f, 0.f, 0.f, 0.f);
            if (row < NROWS)
                xv = *(const float4*)(x + (size_t)row * DD + c4 * 4);
            xv.x = to_tf32(xv.x); xv.y = to_tf32(xv.y);
            xv.z = to_tf32(xv.z); xv.w = to_tf32(xv.w);
            *(float4*)(xt + rr * 132 + c4 * 4) = xv;
        }
    }
    asm volatile("cp.async.wait_group 1;" ::: "memory");
    __syncthreads();

    const int w    = tid >> 5;
    const int lane = tid & 31;
    const int wm   = w & 3;
    const int wn   = w >> 2;
    const int g    = lane >> 2;
    const int tig  = lane & 3;
    const int rowg0 = row0 + wm * 16 + g;

    auto gemm = [&](const float* A, const float* W, float (&acc)[4][4]) {
        #pragma unroll
        for (int nt = 0; nt < 4; nt++)
            #pragma unroll
            for (int rr = 0; rr < 4; rr++) acc[nt][rr] = 0.f;
        const uint32_t* Au = (const uint32_t*)A;
        const uint32_t* Wu = (const uint32_t*)W;
        const int base0 = (wm * 16 + g) * 132;
        #pragma unroll
        for (int ks = 0; ks < 16; ks++) {
            const int kb = ks * 8;
            const uint32_t a0 = Au[base0 + kb + tig];
            const uint32_t a1 = Au[base0 + 8 * 132 + kb + tig];
            const uint32_t a2 = Au[base0 + kb + tig + 4];
            const uint32_t a3 = Au[base0 + 8 * 132 + kb + tig + 4];
            #pragma unroll
            for (int nt = 0; nt < 4; nt++) {
                const int n = wn * 32 + nt * 8 + g;
                const uint32_t b0 = Wu[(kb + tig) * 136 + n];
                const uint32_t b1 = Wu[(kb + tig + 4) * 136 + n];
                mma8(acc[nt][0], acc[nt][1], acc[nt][2], acc[nt][3],
                     a0, a1, a2, a3, b0, b1);
            }
        }
    };

    if (selfmode) {
        float acc[4][4];
        gemm(xs, W0, acc);

        #pragma unroll
        for (int rr = 0; rr < 2; rr++) {
            const int row = rowg0 + rr * 8;
            const bool valid = (row < NROWS);
            const int nodeidx = row % NN;
            const bool hasagg = valid && (nodeidx >= 64);
            const int nbuf = (nodeidx < 192) ? 4 : 8;
            #pragma unroll
            for (int nt = 0; nt < 4; nt++) {
                const int col = wn * 32 + nt * 8 + 2 * tig;
                float c0 = acc[nt][rr * 2 + 0] + __ldg(bself + col);
                float c1 = acc[nt][rr * 2 + 1] + __ldg(bself + col + 1);
                if (hasagg) {
                    const size_t o = (size_t)row * DD + col;
                    for (int cb = 0; cb < nbuf; cb++) {
                        const float2 av = *(const float2*)(g_agg + (size_t)cb * AGG_STRIDE + o);
                        c0 += av.x; c1 += av.y;
                    }
                }
                c0 = fmaxf(c0, 0.f);
                c1 = fmaxf(c1, 0.f);
                if (valid)
                    *(float2*)(g_x + (size_t)row * DD + col) = make_float2(c0, c1);
                *(float2*)(xn + (wm * 16 + g + rr * 8) * 132 + col) =
                    make_float2(to_tf32(c0), to_tf32(c1));
            }
        }
        __syncthreads();
        if (have_uv) {
            stageW(0, msrc + 1);
            asm volatile("cp.async.commit_group;" ::: "memory");
        }
    }

    if (have_uv) {
        asm volatile("cp.async.wait_group 1;" ::: "memory");
        {
            float acc[4][4];
            gemm(xn, selfmode ? W1 : W0, acc);
            #pragma unroll
            for (int rr = 0; rr < 2; rr++) {
                const int row = rowg0 + rr * 8;
                if (row < NROWS) {
                    #pragma unroll
                    for (int nt = 0; nt < 4; nt++) {
                        const int col = wn * 32 + nt * 8 + 2 * tig;
                        *(float2*)(g_u + (size_t)row * DD + col) =
                            make_float2(acc[nt][rr * 2 + 0], acc[nt][rr * 2 + 1]);
                    }
                }
            }
        }
        asm volatile("cp.async.wait_group 0;" ::: "memory");
        __syncthreads();
        {
            float acc[4][4];
            gemm(xn, selfmode ? W0 : W1, acc);
            #pragma unroll
            for (int rr = 0; rr < 2; rr++) {
                const int row = rowg0 + rr * 8;
                if (row < NROWS) {
                    #pragma unroll
                    for (int nt = 0; nt < 4; nt++) {
                        const int col = wn * 32 + nt * 8 + 2 * tig;
                        *(float2*)(g_v + (size_t)row * DD + col) =
                            make_float2(acc[nt][rr * 2 + 0] + __ldg(bnext + col),
                                        acc[nt][rr * 2 + 1] + __ldg(bnext + col + 1));
                    }
                }
            }
        }
    }
}

// ---------------------------------------------------------------------------
// head kernel
// ---------------------------------------------------------------------------
__global__ __launch_bounds__(128) void head_kernel(const float* __restrict__ w1,
                                                   const float* __restrict__ b1,
                                                   const float* __restrict__ w2,
                                                   const float* __restrict__ b2,
                                                   const float* __restrict__ w3,
                                                   const float* __restrict__ b3,
                                                   float* __restrict__ out)
{
    __shared__ float g[128];
    __shared__ float h[128];
    const int b = blockIdx.x;
    const int t = threadIdx.x;

    float s = 0.f;
    const float* xb = g_x + (size_t)b * NN * DD;
    for (int n = 0; n < NN; n++) s += xb[(size_t)n * DD + t];
    g[t] = s * (1.f / (float)NN);
    __syncthreads();

    float acc = 0.f;
    #pragma unroll 4
    for (int k = 0; k < 128; k++) acc += g[k] * __ldg(w1 + k * 128 + t);
    h[t] = fmaxf(acc + b1[t], 0.f);
    __syncthreads();

    acc = 0.f;
    #pragma unroll 4
    for (int k = 0; k < 128; k++) acc += h[k] * __ldg(w2 + k * 128 + t);
    __syncthreads();
    g[t] = fmaxf(acc + b2[t], 0.f);
    __syncthreads();

    if (t < 10) {
        float o = b3[t];
        for (int k = 0; k < 128; k++) o += g[k] * __ldg(w3 + k * 10 + t);
        out[b * 10 + t] = o;
    }
}

// ---------------------------------------------------------------------------
// launch
// ---------------------------------------------------------------------------
extern "C" void kernel_launch(void* const* d_in, const int* in_sizes, int n_in,
                              void* d_out, int out_size)
{
    (void)in_sizes; (void)n_in; (void)out_size;
    const float* node_features = (const float*)d_in[0];
    const float* edge_attr     = (const float*)d_in[1];
    const float* w_msg         = (const float*)d_in[2];
    const float* b_msg         = (const float*)d_in[3];
    const float* w_self        = (const float*)d_in[4];
    const float* b_self        = (const float*)d_in[5];
    const float* w1            = (const float*)d_in[6];
    const float* b1            = (const float*)d_in[7];
    const float* w2            = (const float*)d_in[8];
    const float* b2            = (const float*)d_in[9];
    const float* w3            = (const float*)d_in[10];
    const float* b3            = (const float*)d_in[11];
    float* out = (float*)d_out;

    cudaFuncSetAttribute(edge_kernel, cudaFuncAttributeMaxDynamicSharedMemorySize,
                         EDGE_SMEM_BYTES);
    cudaFuncSetAttribute(self_uv_tf32, cudaFuncAttributeMaxDynamicSharedMemorySize,
                         SV_SMEM_BYTES);

    prepack_wt<<<9, 256>>>(w_self, w_msg);

    // layer-0: uv-only mode (msrc = matrix idx of layer-0 Wsrc = 1)
    self_uv_tf32<<<115, 512, SV_SMEM_BYTES>>>(node_features, -1, nullptr, 1, b_msg);

    for (int l = 0; l < 3; l++) {
        const float* wl = w_msg + (size_t)l * 384 * 128;
        // layer 0: async fp32 staging + inline bf16 conversion (persists g_ebf)
        edge_kernel<<<EDGE_GRID, 512, EDGE_SMEM_BYTES>>>(
            wl, (l == 0) ? edge_attr : nullptr);

        const float* xin = (l == 0) ? node_features : nullptr;
        const int msrc = (l < 2) ? (3 * (l + 1) + 1) : -1;
        const float* bn = (l < 2) ? (b_msg + (size_t)(l + 1) * 128) : nullptr;
        self_uv_tf32<<<115, 512, SV_SMEM_BYTES>>>(xin, 3 * l,
                                                  b_self + (size_t)l * 128, msrc, bn);
    }
    head_kernel<<<16, 128>>>(w1, b1, w2, b2, w3, b3, out);
}